// round 10
// baseline (speedup 1.0000x reference)
#include <cuda_runtime.h>
#include <cuda_fp16.h>
#include <cstdint>

#define N_NODES 100000
#define N_EDGES 1600000
#define EMB 128
#define HID 128
#define REPR 64
#define CAT 384

#define SCAN_B 256
#define SCAN_NBLK ((N_NODES + SCAN_B - 1) / SCAN_B)   // 391

// Scratch (device globals; no allocation APIs allowed)
__device__ int    g_is64;
__device__ int    g_cnt   [N_NODES];
__device__ int    g_cursor[N_NODES];
__device__ int    g_ro    [N_NODES];
__device__ int    g_adj   [N_EDGES];
__device__ int    g_bsum  [SCAN_NBLK];
__device__ int    g_boff  [SCAN_NBLK];
__device__ float  g_dinv  [N_NODES];
__device__ __half g_h1h   [(size_t)N_NODES * HID];  // fp16: (A@W) * dinv[row]
__device__ __half g_xsh   [(size_t)N_NODES * CAT];  // fp16 JumpingKnowledge concat

// ---------------------------------------------------------------------------
// fp16 MMA m16n8k16, fp32 accumulate
// ---------------------------------------------------------------------------
__device__ __forceinline__ void mma_f16(float c[4], const uint32_t a[4],
                                        uint32_t b0, uint32_t b1) {
    asm volatile(
        "mma.sync.aligned.m16n8k16.row.col.f32.f16.f16.f32 "
        "{%0,%1,%2,%3}, {%4,%5,%6,%7}, {%8,%9}, {%0,%1,%2,%3};"
        : "+f"(c[0]), "+f"(c[1]), "+f"(c[2]), "+f"(c[3])
        : "r"(a[0]), "r"(a[1]), "r"(a[2]), "r"(a[3]), "r"(b0), "r"(b1));
}

// ---------------------------------------------------------------------------
// Edge-index dtype probe: int64 nonneg values < 2^32 have zero high words.
// ---------------------------------------------------------------------------
__global__ void k_detect(const int* __restrict__ ei32) {
    if (blockIdx.x == 0 && threadIdx.x == 0) {
        int is64 = 1;
        for (int i = 0; i < 256; i++) {
            if (ei32[2 * i + 1] != 0) { is64 = 0; break; }
        }
        g_is64 = is64;
    }
}

__device__ __forceinline__ int edge_at(const void* ei, int idx) {
    if (g_is64) return (int)((const long long*)ei)[idx];
    return ((const int*)ei)[idx];
}

// ---------------------------------------------------------------------------
// CSR build
// ---------------------------------------------------------------------------
__global__ void k_zero_counts() {
    int i = blockIdx.x * blockDim.x + threadIdx.x;
    if (i < N_NODES) { g_cnt[i] = 0; g_cursor[i] = 0; }
}

__global__ void k_count(const void* __restrict__ ei) {
    int e = blockIdx.x * blockDim.x + threadIdx.x;
    if (e < N_EDGES) {
        int c = edge_at(ei, N_EDGES + e);
        atomicAdd(&g_cnt[c], 1);
    }
}

__global__ void __launch_bounds__(SCAN_B) k_block_sums() {
    __shared__ int sdata[SCAN_B];
    int i = blockIdx.x * SCAN_B + threadIdx.x;
    int v = (i < N_NODES) ? g_cnt[i] : 0;
    sdata[threadIdx.x] = v;
    __syncthreads();
#pragma unroll
    for (int off = SCAN_B / 2; off > 0; off >>= 1) {
        if (threadIdx.x < off) sdata[threadIdx.x] += sdata[threadIdx.x + off];
        __syncthreads();
    }
    if (threadIdx.x == 0) g_bsum[blockIdx.x] = sdata[0];
}

__global__ void __launch_bounds__(512) k_scan_bsums() {
    __shared__ int s[512];
    int t = threadIdx.x;
    int v = (t < SCAN_NBLK) ? g_bsum[t] : 0;
    s[t] = v;
    __syncthreads();
    for (int off = 1; off < 512; off <<= 1) {
        int u = (t >= off) ? s[t - off] : 0;
        __syncthreads();
        s[t] += u;
        __syncthreads();
    }
    if (t < SCAN_NBLK) g_boff[t] = s[t] - v;   // exclusive
}

__global__ void __launch_bounds__(SCAN_B) k_scan_final() {
    __shared__ int s[SCAN_B];
    int t = threadIdx.x;
    int i = blockIdx.x * SCAN_B + t;
    int v = (i < N_NODES) ? g_cnt[i] : 0;
    s[t] = v;
    __syncthreads();
    for (int off = 1; off < SCAN_B; off <<= 1) {
        int u = (t >= off) ? s[t - off] : 0;
        __syncthreads();
        s[t] += u;
        __syncthreads();
    }
    if (i < N_NODES) {
        g_ro[i]   = g_boff[blockIdx.x] + s[t] - v;   // exclusive
        g_dinv[i] = rsqrtf(1.0f + (float)v);
    }
}

__global__ void k_csr_fill(const void* __restrict__ ei) {
    int e = blockIdx.x * blockDim.x + threadIdx.x;
    if (e < N_EDGES) {
        int r = edge_at(ei, e);
        int c = edge_at(ei, N_EDGES + e);
        int pos = atomicAdd(&g_cursor[c], 1);
        g_adj[g_ro[c] + pos] = r;
    }
}

// ---------------------------------------------------------------------------
// Layer GEMM (fp16 MMA m16n8k16): h1h = fp16( (A @ W) * dinv[row] )
// Block 128x128, BK=32, 8 warps as 4(m) x 2(n); warp tile 32x64.
// As[m][k] half pad 40; Wt[n][k] half pad 40 (W transposed at tile load).
// ---------------------------------------------------------------------------
__global__ void __launch_bounds__(256) k_gemm_layer(
    const float* __restrict__ x, int layer,
    const float* __restrict__ W)
{
    __shared__ __half As[128][40];
    __shared__ __half Wt[128][40];

    const int row0   = blockIdx.x * 128;
    const int tid    = threadIdx.x;
    const int wid    = tid >> 5;
    const int lane   = tid & 31;
    const int g      = lane >> 2;     // 0..7
    const int t      = lane & 3;      // 0..3
    const int warp_m = wid >> 1;      // 0..3
    const int warp_n = wid & 1;       // 0..1

    const __half* Ah = (layer > 0) ? (g_xsh + (layer - 1) * HID) : nullptr;

    float acc[2][8][4];
#pragma unroll
    for (int mt = 0; mt < 2; mt++)
#pragma unroll
        for (int nt = 0; nt < 8; nt++)
#pragma unroll
            for (int q = 0; q < 4; q++) acc[mt][nt][q] = 0.0f;

    for (int k0 = 0; k0 < 128; k0 += 32) {
        // A tile 128x32 halfs: 1024 chunks of 4 halfs, 4 per thread
#pragma unroll
        for (int p = 0; p < 4; p++) {
            int idx = tid + p * 256;
            int r   = idx >> 3;
            int c4  = (idx & 7) << 2;   // half offset, multiple of 4
            int gr  = row0 + r;
            uint2 u = make_uint2(0u, 0u);
            if (gr < N_NODES) {
                if (layer == 0) {
                    float4 v = *(const float4*)(x + (size_t)gr * EMB + k0 + c4);
                    __half2 h0 = __floats2half2_rn(v.x, v.y);
                    __half2 h1 = __floats2half2_rn(v.z, v.w);
                    u.x = *(uint32_t*)&h0;
                    u.y = *(uint32_t*)&h1;
                } else {
                    u = *(const uint2*)(Ah + (size_t)gr * CAT + k0 + c4);
                }
            }
            *(uint2*)&As[r][c4] = u;
        }
        // W tile 32x128 fp32 -> transposed half Wt[n][k]
#pragma unroll
        for (int p = 0; p < 4; p++) {
            int idx = tid + p * 256;
            int r   = idx >> 5;            // k row 0..31
            int c4  = (idx & 31) << 2;     // n col, multiple of 4
            float4 v = *(const float4*)(W + (size_t)(k0 + r) * 128 + c4);
            Wt[c4 + 0][r] = __float2half_rn(v.x);
            Wt[c4 + 1][r] = __float2half_rn(v.y);
            Wt[c4 + 2][r] = __float2half_rn(v.z);
            Wt[c4 + 3][r] = __float2half_rn(v.w);
        }
        __syncthreads();

#pragma unroll
        for (int kc = 0; kc < 2; kc++) {
            int kb = kc * 16;
            uint32_t afr[2][4];
#pragma unroll
            for (int mt = 0; mt < 2; mt++) {
                int mrow = warp_m * 32 + mt * 16;
                afr[mt][0] = *(const uint32_t*)&As[mrow + g    ][kb + 2 * t    ];
                afr[mt][1] = *(const uint32_t*)&As[mrow + g + 8][kb + 2 * t    ];
                afr[mt][2] = *(const uint32_t*)&As[mrow + g    ][kb + 2 * t + 8];
                afr[mt][3] = *(const uint32_t*)&As[mrow + g + 8][kb + 2 * t + 8];
            }
#pragma unroll
            for (int nt = 0; nt < 8; nt++) {
                int nc = warp_n * 64 + nt * 8;
                uint32_t b0 = *(const uint32_t*)&Wt[nc + g][kb + 2 * t    ];
                uint32_t b1 = *(const uint32_t*)&Wt[nc + g][kb + 2 * t + 8];
                mma_f16(acc[0][nt], afr[0], b0, b1);
                mma_f16(acc[1][nt], afr[1], b0, b1);
            }
        }
        __syncthreads();
    }

    // Epilogue: scale by dinv[row], convert to fp16, store half2 pairs
#pragma unroll
    for (int mt = 0; mt < 2; mt++) {
        int r0 = row0 + warp_m * 32 + mt * 16 + g;
        int r1 = r0 + 8;
        bool ok0 = (r0 < N_NODES), ok1 = (r1 < N_NODES);
        float d0 = ok0 ? g_dinv[r0] : 0.f;
        float d1 = ok1 ? g_dinv[r1] : 0.f;
#pragma unroll
        for (int nt = 0; nt < 8; nt++) {
            int col = warp_n * 64 + nt * 8 + 2 * t;
            if (ok0) {
                __half2 h = __floats2half2_rn(acc[mt][nt][0] * d0, acc[mt][nt][1] * d0);
                *(__half2*)(g_h1h + (size_t)r0 * 128 + col) = h;
            }
            if (ok1) {
                __half2 h = __floats2half2_rn(acc[mt][nt][2] * d1, acc[mt][nt][3] * d1);
                *(__half2*)(g_h1h + (size_t)r1 * 128 + col) = h;
            }
        }
    }
}

// ---------------------------------------------------------------------------
// Gather aggregation: one warp per node; lane holds 4 features (uint2 = 2x
// half2 per row). Accumulate fp32. Output fp16 into g_xsh.
// ---------------------------------------------------------------------------
__global__ void __launch_bounds__(256) k_gather(
    const float* __restrict__ b, int layer)
{
    int w    = (blockIdx.x * 256 + threadIdx.x) >> 5;
    int lane = threadIdx.x & 31;
    if (w >= N_NODES) return;

    float4 acc;
    {
        uint2 u = ((const uint2*)(g_h1h + (size_t)w * 128))[lane];
        float2 f0 = __half22float2(*(__half2*)&u.x);
        float2 f1 = __half22float2(*(__half2*)&u.y);
        acc = make_float4(f0.x, f0.y, f1.x, f1.y);
    }

    int start = g_ro[w];
    int deg   = g_cnt[w];

    int k = 0;
    for (; k + 3 < deg; k += 4) {
        int n0 = g_adj[start + k];
        int n1 = g_adj[start + k + 1];
        int n2 = g_adj[start + k + 2];
        int n3 = g_adj[start + k + 3];
        uint2 u0 = ((const uint2*)(g_h1h + (size_t)n0 * 128))[lane];
        uint2 u1 = ((const uint2*)(g_h1h + (size_t)n1 * 128))[lane];
        uint2 u2 = ((const uint2*)(g_h1h + (size_t)n2 * 128))[lane];
        uint2 u3 = ((const uint2*)(g_h1h + (size_t)n3 * 128))[lane];
        float2 a0 = __half22float2(*(__half2*)&u0.x), b0 = __half22float2(*(__half2*)&u0.y);
        float2 a1 = __half22float2(*(__half2*)&u1.x), b1f = __half22float2(*(__half2*)&u1.y);
        float2 a2 = __half22float2(*(__half2*)&u2.x), b2 = __half22float2(*(__half2*)&u2.y);
        float2 a3 = __half22float2(*(__half2*)&u3.x), b3 = __half22float2(*(__half2*)&u3.y);
        acc.x += (a0.x + a1.x) + (a2.x + a3.x);
        acc.y += (a0.y + a1.y) + (a2.y + a3.y);
        acc.z += (b0.x + b1f.x) + (b2.x + b3.x);
        acc.w += (b0.y + b1f.y) + (b2.y + b3.y);
    }
    for (; k < deg; k++) {
        int n0 = g_adj[start + k];
        uint2 u0 = ((const uint2*)(g_h1h + (size_t)n0 * 128))[lane];
        float2 a0 = __half22float2(*(__half2*)&u0.x);
        float2 b0 = __half22float2(*(__half2*)&u0.y);
        acc.x += a0.x; acc.y += a0.y; acc.z += b0.x; acc.w += b0.y;
    }

    float d = g_dinv[w];
    float4 bv = ((const float4*)b)[lane];
    float4 r;
    r.x = fmaxf(fmaf(acc.x, d, bv.x), 0.f);
    r.y = fmaxf(fmaf(acc.y, d, bv.y), 0.f);
    r.z = fmaxf(fmaf(acc.z, d, bv.z), 0.f);
    r.w = fmaxf(fmaf(acc.w, d, bv.w), 0.f);

    uint2 o;
    __half2 h0 = __floats2half2_rn(r.x, r.y);
    __half2 h1 = __floats2half2_rn(r.z, r.w);
    o.x = *(uint32_t*)&h0;
    o.y = *(uint32_t*)&h1;
    *((uint2*)(g_xsh + (size_t)w * CAT + layer * HID) + lane) = o;
}

// ---------------------------------------------------------------------------
// Final GEMM (fp16 MMA): out = xsh @ Wlin + blin  (xsh: [M,384] fp16)
// Block 128x64, BK=32, 8 warps as 8(m) x 1(n); warp tile 16x64.
// ---------------------------------------------------------------------------
__global__ void __launch_bounds__(256) k_gemm_final(
    const float* __restrict__ W,
    const float* __restrict__ b,
    float* __restrict__ out)
{
    __shared__ __half As[128][40];
    __shared__ __half Wt[64][40];

    const int row0 = blockIdx.x * 128;
    const int tid  = threadIdx.x;
    const int wid  = tid >> 5;
    const int lane = tid & 31;
    const int g    = lane >> 2;
    const int t    = lane & 3;

    float acc[8][4];
#pragma unroll
    for (int nt = 0; nt < 8; nt++)
#pragma unroll
        for (int q = 0; q < 4; q++) acc[nt][q] = 0.0f;

    for (int k0 = 0; k0 < CAT; k0 += 32) {
        // A tile 128x32 halfs from g_xsh
#pragma unroll
        for (int p = 0; p < 4; p++) {
            int idx = tid + p * 256;
            int r   = idx >> 3;
            int c4  = (idx & 7) << 2;
            int gr  = row0 + r;
            uint2 u = make_uint2(0u, 0u);
            if (gr < N_NODES)
                u = *(const uint2*)(g_xsh + (size_t)gr * CAT + k0 + c4);
            *(uint2*)&As[r][c4] = u;
        }
        // W tile 32x64 fp32 -> transposed half Wt[n][k]
#pragma unroll
        for (int p = 0; p < 2; p++) {
            int idx = tid + p * 256;
            int r   = idx >> 4;            // k row 0..31
            int c4  = (idx & 15) << 2;     // n col
            float4 v = *(const float4*)(W + (size_t)(k0 + r) * REPR + c4);
            Wt[c4 + 0][r] = __float2half_rn(v.x);
            Wt[c4 + 1][r] = __float2half_rn(v.y);
            Wt[c4 + 2][r] = __float2half_rn(v.z);
            Wt[c4 + 3][r] = __float2half_rn(v.w);
        }
        __syncthreads();

#pragma unroll
        for (int kc = 0; kc < 2; kc++) {
            int kb = kc * 16;
            uint32_t afr[4];
            int mrow = wid * 16;
            afr[0] = *(const uint32_t*)&As[mrow + g    ][kb + 2 * t    ];
            afr[1] = *(const uint32_t*)&As[mrow + g + 8][kb + 2 * t    ];
            afr[2] = *(const uint32_t*)&As[mrow + g    ][kb + 2 * t + 8];
            afr[3] = *(const uint32_t*)&As[mrow + g + 8][kb + 2 * t + 8];
#pragma unroll
            for (int nt = 0; nt < 8; nt++) {
                int nc = nt * 8;
                uint32_t b0 = *(const uint32_t*)&Wt[nc + g][kb + 2 * t    ];
                uint32_t b1 = *(const uint32_t*)&Wt[nc + g][kb + 2 * t + 8];
                mma_f16(acc[nt], afr, b0, b1);
            }
        }
        __syncthreads();
    }

    int r0 = row0 + wid * 16 + g;
    int r1 = r0 + 8;
    bool ok0 = (r0 < N_NODES), ok1 = (r1 < N_NODES);
#pragma unroll
    for (int nt = 0; nt < 8; nt++) {
        int col = nt * 8 + 2 * t;
        float2 bv = *(const float2*)(b + col);
        if (ok0) {
            float2 v = make_float2(acc[nt][0] + bv.x, acc[nt][1] + bv.y);
            *(float2*)(out + (size_t)r0 * REPR + col) = v;
        }
        if (ok1) {
            float2 v = make_float2(acc[nt][2] + bv.x, acc[nt][3] + bv.y);
            *(float2*)(out + (size_t)r1 * REPR + col) = v;
        }
    }
}

// ---------------------------------------------------------------------------
// Launch
// ---------------------------------------------------------------------------
extern "C" void kernel_launch(void* const* d_in, const int* in_sizes, int n_in,
                              void* d_out, int out_size)
{
    const float* x    = (const float*)d_in[0];
    const void*  ei   = d_in[1];
    const float* W1   = (const float*)d_in[2];
    const float* b1   = (const float*)d_in[3];
    const float* W2   = (const float*)d_in[4];
    const float* b2   = (const float*)d_in[5];
    const float* W3   = (const float*)d_in[6];
    const float* b3   = (const float*)d_in[7];
    const float* Wlin = (const float*)d_in[8];
    const float* blin = (const float*)d_in[9];
    float*       out  = (float*)d_out;

    const int node_blocks = (N_NODES + 255) / 256;
    const int edge_blocks = (N_EDGES + 255) / 256;
    const int gemm_blocks = (N_NODES + 127) / 128;
    const int warp_blocks = (N_NODES * 32 + 255) / 256;

    k_detect     <<<1, 32>>>((const int*)ei);
    k_zero_counts<<<node_blocks, 256>>>();
    k_count      <<<edge_blocks, 256>>>(ei);
    k_block_sums <<<SCAN_NBLK, SCAN_B>>>();
    k_scan_bsums <<<1, 512>>>();
    k_scan_final <<<SCAN_NBLK, SCAN_B>>>();
    k_csr_fill   <<<edge_blocks, 256>>>(ei);

    const float* Wl[3] = {W1, W2, W3};
    const float* bl[3] = {b1, b2, b3};
    for (int l = 0; l < 3; l++) {
        k_gemm_layer<<<gemm_blocks, 256>>>(x, l, Wl[l]);
        k_gather    <<<warp_blocks, 256>>>(bl[l], l);
    }

    k_gemm_final<<<gemm_blocks, 256>>>(Wlin, blin, out);
}

// round 11
// speedup vs baseline: 1.0360x; 1.0360x over previous
#include <cuda_runtime.h>
#include <cuda_fp16.h>
#include <cstdint>

#define N_NODES 100000
#define N_EDGES 1600000
#define EMB 128
#define HID 128
#define REPR 64
#define CAT 384

#define SCAN_B 256
#define SCAN_NBLK ((N_NODES + SCAN_B - 1) / SCAN_B)   // 391

// Scratch (device globals; no allocation APIs allowed)
__device__ int    g_is64;
__device__ int    g_cnt   [N_NODES];
__device__ int    g_cursor[N_NODES];
__device__ int    g_ro    [N_NODES];
__device__ int    g_adj   [N_EDGES];
__device__ int    g_bsum  [SCAN_NBLK];
__device__ int    g_boff  [SCAN_NBLK];
__device__ float  g_dinv  [N_NODES];
__device__ __half g_h1h   [(size_t)N_NODES * HID];  // fp16: (A@W) * dinv[row]
__device__ __half g_xsh   [(size_t)N_NODES * CAT];  // fp16 JumpingKnowledge concat

// ---------------------------------------------------------------------------
// Helpers
// ---------------------------------------------------------------------------
__device__ __forceinline__ uint32_t tf32r(float f) {
    uint32_t u;
    asm("cvt.rna.tf32.f32 %0, %1;" : "=r"(u) : "f"(f));
    return u;
}

__device__ __forceinline__ void mma_tf32(float c[4], const uint32_t a[4],
                                         uint32_t b0, uint32_t b1) {
    asm volatile(
        "mma.sync.aligned.m16n8k8.row.col.f32.tf32.tf32.f32 "
        "{%0,%1,%2,%3}, {%4,%5,%6,%7}, {%8,%9}, {%0,%1,%2,%3};"
        : "+f"(c[0]), "+f"(c[1]), "+f"(c[2]), "+f"(c[3])
        : "r"(a[0]), "r"(a[1]), "r"(a[2]), "r"(a[3]), "r"(b0), "r"(b1));
}

__device__ __forceinline__ int edge_at(const void* ei, int idx) {
    if (g_is64) return (int)((const long long*)ei)[idx];
    return ((const int*)ei)[idx];
}

// ---------------------------------------------------------------------------
// Prep: zero counters; block 0 thread 0 also probes the edge-index dtype
// (int64 nonneg values < 2^32 have zero high words).
// ---------------------------------------------------------------------------
__global__ void k_prep(const int* __restrict__ ei32) {
    int i = blockIdx.x * blockDim.x + threadIdx.x;
    if (i < N_NODES) { g_cnt[i] = 0; g_cursor[i] = 0; }
    if (blockIdx.x == 0 && threadIdx.x == 0) {
        int is64 = 1;
        for (int k = 0; k < 256; k++) {
            if (ei32[2 * k + 1] != 0) { is64 = 0; break; }
        }
        g_is64 = is64;
    }
}

__global__ void k_count(const void* __restrict__ ei) {
    int e = blockIdx.x * blockDim.x + threadIdx.x;
    if (e < N_EDGES) {
        int c = edge_at(ei, N_EDGES + e);
        atomicAdd(&g_cnt[c], 1);
    }
}

__global__ void __launch_bounds__(SCAN_B) k_block_sums() {
    __shared__ int sdata[SCAN_B];
    int i = blockIdx.x * SCAN_B + threadIdx.x;
    int v = (i < N_NODES) ? g_cnt[i] : 0;
    sdata[threadIdx.x] = v;
    __syncthreads();
#pragma unroll
    for (int off = SCAN_B / 2; off > 0; off >>= 1) {
        if (threadIdx.x < off) sdata[threadIdx.x] += sdata[threadIdx.x + off];
        __syncthreads();
    }
    if (threadIdx.x == 0) g_bsum[blockIdx.x] = sdata[0];
}

__global__ void __launch_bounds__(512) k_scan_bsums() {
    __shared__ int s[512];
    int t = threadIdx.x;
    int v = (t < SCAN_NBLK) ? g_bsum[t] : 0;
    s[t] = v;
    __syncthreads();
    for (int off = 1; off < 512; off <<= 1) {
        int u = (t >= off) ? s[t - off] : 0;
        __syncthreads();
        s[t] += u;
        __syncthreads();
    }
    if (t < SCAN_NBLK) g_boff[t] = s[t] - v;   // exclusive
}

__global__ void __launch_bounds__(SCAN_B) k_scan_final() {
    __shared__ int s[SCAN_B];
    int t = threadIdx.x;
    int i = blockIdx.x * SCAN_B + t;
    int v = (i < N_NODES) ? g_cnt[i] : 0;
    s[t] = v;
    __syncthreads();
    for (int off = 1; off < SCAN_B; off <<= 1) {
        int u = (t >= off) ? s[t - off] : 0;
        __syncthreads();
        s[t] += u;
        __syncthreads();
    }
    if (i < N_NODES) {
        g_ro[i]   = g_boff[blockIdx.x] + s[t] - v;   // exclusive
        g_dinv[i] = rsqrtf(1.0f + (float)v);
    }
}

__global__ void k_csr_fill(const void* __restrict__ ei) {
    int e = blockIdx.x * blockDim.x + threadIdx.x;
    if (e < N_EDGES) {
        int r = edge_at(ei, e);
        int c = edge_at(ei, N_EDGES + e);
        int pos = atomicAdd(&g_cursor[c], 1);
        g_adj[g_ro[c] + pos] = r;
    }
}

// ---------------------------------------------------------------------------
// Layer GEMM (tf32 tensor cores): h1h = fp16( (A @ W) * dinv[row] )
// layer 0: A = x (fp32); layer > 0: A = g_xsh slice (fp16, exact in tf32)
// Block 128x128, BK=32, 8 warps as 4(m) x 2(n); warp tile 32x64.
// ---------------------------------------------------------------------------
__global__ void __launch_bounds__(256) k_gemm_layer(
    const float* __restrict__ x, int layer,
    const float* __restrict__ W)
{
    __shared__ float As[128][36];
    __shared__ float Ws[32][132];

    const int row0   = blockIdx.x * 128;
    const int tid    = threadIdx.x;
    const int wid    = tid >> 5;
    const int lane   = tid & 31;
    const int g      = lane >> 2;     // groupID 0..7
    const int t      = lane & 3;      // threadID in group 0..3
    const int warp_m = wid >> 1;      // 0..3
    const int warp_n = wid & 1;       // 0..1

    const __half* Ah = (layer > 0) ? (g_xsh + (layer - 1) * HID) : nullptr;

    float acc[2][8][4];
#pragma unroll
    for (int mt = 0; mt < 2; mt++)
#pragma unroll
        for (int nt = 0; nt < 8; nt++)
#pragma unroll
            for (int q = 0; q < 4; q++) acc[mt][nt][q] = 0.0f;

    for (int k0 = 0; k0 < 128; k0 += 32) {
        // A tile 128x32 (4 slots per thread)
#pragma unroll
        for (int p = 0; p < 4; p++) {
            int idx = tid + p * 256;
            int r   = idx >> 3;
            int c4  = (idx & 7) << 2;
            int gr  = row0 + r;
            float4 v = make_float4(0.f, 0.f, 0.f, 0.f);
            if (gr < N_NODES) {
                if (layer == 0) {
                    v = *(const float4*)(x + (size_t)gr * EMB + k0 + c4);
                    v.x = __uint_as_float(tf32r(v.x));
                    v.y = __uint_as_float(tf32r(v.y));
                    v.z = __uint_as_float(tf32r(v.z));
                    v.w = __uint_as_float(tf32r(v.w));
                } else {
                    uint2 u = *(const uint2*)(Ah + (size_t)gr * CAT + k0 + c4);
                    float2 f0 = __half22float2(*(__half2*)&u.x);
                    float2 f1 = __half22float2(*(__half2*)&u.y);
                    v = make_float4(f0.x, f0.y, f1.x, f1.y);
                }
            }
            *(float4*)&As[r][c4] = v;
        }
        // W tile 32x128 (fp32 external)
#pragma unroll
        for (int p = 0; p < 4; p++) {
            int idx = tid + p * 256;
            int r   = idx >> 5;
            int c4  = (idx & 31) << 2;
            float4 v = *(const float4*)(W + (size_t)(k0 + r) * 128 + c4);
            v.x = __uint_as_float(tf32r(v.x));
            v.y = __uint_as_float(tf32r(v.y));
            v.z = __uint_as_float(tf32r(v.z));
            v.w = __uint_as_float(tf32r(v.w));
            *(float4*)&Ws[r][c4] = v;
        }
        __syncthreads();

#pragma unroll
        for (int kc = 0; kc < 4; kc++) {
            int kb = kc * 8;
            uint32_t afr[2][4];
#pragma unroll
            for (int mt = 0; mt < 2; mt++) {
                int mrow = warp_m * 32 + mt * 16;
                afr[mt][0] = __float_as_uint(As[mrow + g    ][kb + t    ]);
                afr[mt][1] = __float_as_uint(As[mrow + g + 8][kb + t    ]);
                afr[mt][2] = __float_as_uint(As[mrow + g    ][kb + t + 4]);
                afr[mt][3] = __float_as_uint(As[mrow + g + 8][kb + t + 4]);
            }
#pragma unroll
            for (int nt = 0; nt < 8; nt++) {
                int nc = warp_n * 64 + nt * 8;
                uint32_t b0 = __float_as_uint(Ws[kb + t    ][nc + g]);
                uint32_t b1 = __float_as_uint(Ws[kb + t + 4][nc + g]);
                mma_tf32(acc[0][nt], afr[0], b0, b1);
                mma_tf32(acc[1][nt], afr[1], b0, b1);
            }
        }
        __syncthreads();
    }

    // Epilogue: scale by dinv[row], convert to fp16, store half2 pairs
#pragma unroll
    for (int mt = 0; mt < 2; mt++) {
        int r0 = row0 + warp_m * 32 + mt * 16 + g;
        int r1 = r0 + 8;
        bool ok0 = (r0 < N_NODES), ok1 = (r1 < N_NODES);
        float d0 = ok0 ? g_dinv[r0] : 0.f;
        float d1 = ok1 ? g_dinv[r1] : 0.f;
#pragma unroll
        for (int nt = 0; nt < 8; nt++) {
            int col = warp_n * 64 + nt * 8 + 2 * t;
            if (ok0) {
                __half2 h = __floats2half2_rn(acc[mt][nt][0] * d0, acc[mt][nt][1] * d0);
                *(__half2*)(g_h1h + (size_t)r0 * 128 + col) = h;
            }
            if (ok1) {
                __half2 h = __floats2half2_rn(acc[mt][nt][2] * d1, acc[mt][nt][3] * d1);
                *(__half2*)(g_h1h + (size_t)r1 * 128 + col) = h;
            }
        }
    }
}

// ---------------------------------------------------------------------------
// Gather aggregation: one warp per node; lane holds 4 features (uint2 = 2x
// half2). Accumulate fp32. Unroll 8 for MLP. Output fp16 into g_xsh.
// ---------------------------------------------------------------------------
__global__ void __launch_bounds__(256) k_gather(
    const float* __restrict__ b, int layer)
{
    int w    = (blockIdx.x * 256 + threadIdx.x) >> 5;
    int lane = threadIdx.x & 31;
    if (w >= N_NODES) return;

    float4 acc;
    {
        uint2 u = ((const uint2*)(g_h1h + (size_t)w * 128))[lane];
        float2 f0 = __half22float2(*(__half2*)&u.x);
        float2 f1 = __half22float2(*(__half2*)&u.y);
        acc = make_float4(f0.x, f0.y, f1.x, f1.y);
    }

    int start = g_ro[w];
    int deg   = g_cnt[w];

    int k = 0;
    for (; k + 7 < deg; k += 8) {
        int n[8];
#pragma unroll
        for (int j = 0; j < 8; j++) n[j] = g_adj[start + k + j];
        uint2 u[8];
#pragma unroll
        for (int j = 0; j < 8; j++)
            u[j] = ((const uint2*)(g_h1h + (size_t)n[j] * 128))[lane];
#pragma unroll
        for (int j = 0; j < 8; j++) {
            float2 f0 = __half22float2(*(__half2*)&u[j].x);
            float2 f1 = __half22float2(*(__half2*)&u[j].y);
            acc.x += f0.x; acc.y += f0.y; acc.z += f1.x; acc.w += f1.y;
        }
    }
    for (; k + 3 < deg; k += 4) {
        int n[4];
#pragma unroll
        for (int j = 0; j < 4; j++) n[j] = g_adj[start + k + j];
        uint2 u[4];
#pragma unroll
        for (int j = 0; j < 4; j++)
            u[j] = ((const uint2*)(g_h1h + (size_t)n[j] * 128))[lane];
#pragma unroll
        for (int j = 0; j < 4; j++) {
            float2 f0 = __half22float2(*(__half2*)&u[j].x);
            float2 f1 = __half22float2(*(__half2*)&u[j].y);
            acc.x += f0.x; acc.y += f0.y; acc.z += f1.x; acc.w += f1.y;
        }
    }
    for (; k < deg; k++) {
        int n0 = g_adj[start + k];
        uint2 u0 = ((const uint2*)(g_h1h + (size_t)n0 * 128))[lane];
        float2 f0 = __half22float2(*(__half2*)&u0.x);
        float2 f1 = __half22float2(*(__half2*)&u0.y);
        acc.x += f0.x; acc.y += f0.y; acc.z += f1.x; acc.w += f1.y;
    }

    float d = g_dinv[w];
    float4 bv = ((const float4*)b)[lane];
    float4 r;
    r.x = fmaxf(fmaf(acc.x, d, bv.x), 0.f);
    r.y = fmaxf(fmaf(acc.y, d, bv.y), 0.f);
    r.z = fmaxf(fmaf(acc.z, d, bv.z), 0.f);
    r.w = fmaxf(fmaf(acc.w, d, bv.w), 0.f);

    uint2 o;
    __half2 h0 = __floats2half2_rn(r.x, r.y);
    __half2 h1 = __floats2half2_rn(r.z, r.w);
    o.x = *(uint32_t*)&h0;
    o.y = *(uint32_t*)&h1;
    *((uint2*)(g_xsh + (size_t)w * CAT + layer * HID) + lane) = o;
}

// ---------------------------------------------------------------------------
// Final GEMM (tf32): out = xsh @ Wlin + blin  (xsh: [M,384] fp16)
// Block 128x64, BK=32, 8 warps as 8(m) x 1(n); warp tile 16x64.
// ---------------------------------------------------------------------------
__global__ void __launch_bounds__(256) k_gemm_final(
    const float* __restrict__ W,
    const float* __restrict__ b,
    float* __restrict__ out)
{
    __shared__ float As[128][36];
    __shared__ float Ws[32][68];

    const int row0 = blockIdx.x * 128;
    const int tid  = threadIdx.x;
    const int wid  = tid >> 5;
    const int lane = tid & 31;
    const int g    = lane >> 2;
    const int t    = lane & 3;

    float acc[8][4];
#pragma unroll
    for (int nt = 0; nt < 8; nt++)
#pragma unroll
        for (int q = 0; q < 4; q++) acc[nt][q] = 0.0f;

    for (int k0 = 0; k0 < CAT; k0 += 32) {
#pragma unroll
        for (int p = 0; p < 4; p++) {
            int idx = tid + p * 256;
            int r   = idx >> 3;
            int c4  = (idx & 7) << 2;
            int gr  = row0 + r;
            float4 v = make_float4(0.f, 0.f, 0.f, 0.f);
            if (gr < N_NODES) {
                uint2 u = *(const uint2*)(g_xsh + (size_t)gr * CAT + k0 + c4);
                float2 f0 = __half22float2(*(__half2*)&u.x);
                float2 f1 = __half22float2(*(__half2*)&u.y);
                v = make_float4(f0.x, f0.y, f1.x, f1.y);
            }
            *(float4*)&As[r][c4] = v;
        }
#pragma unroll
        for (int p = 0; p < 2; p++) {
            int idx = tid + p * 256;
            int r   = idx >> 4;
            int c4  = (idx & 15) << 2;
            float4 v = *(const float4*)(W + (size_t)(k0 + r) * REPR + c4);
            v.x = __uint_as_float(tf32r(v.x));
            v.y = __uint_as_float(tf32r(v.y));
            v.z = __uint_as_float(tf32r(v.z));
            v.w = __uint_as_float(tf32r(v.w));
            *(float4*)&Ws[r][c4] = v;
        }
        __syncthreads();

#pragma unroll
        for (int kc = 0; kc < 4; kc++) {
            int kb = kc * 8;
            uint32_t afr[4];
            int mrow = wid * 16;
            afr[0] = __float_as_uint(As[mrow + g    ][kb + t    ]);
            afr[1] = __float_as_uint(As[mrow + g + 8][kb + t    ]);
            afr[2] = __float_as_uint(As[mrow + g    ][kb + t + 4]);
            afr[3] = __float_as_uint(As[mrow + g + 8][kb + t + 4]);
#pragma unroll
            for (int nt = 0; nt < 8; nt++) {
                int nc = nt * 8;
                uint32_t b0 = __float_as_uint(Ws[kb + t    ][nc + g]);
                uint32_t b1 = __float_as_uint(Ws[kb + t + 4][nc + g]);
                mma_tf32(acc[nt], afr, b0, b1);
            }
        }
        __syncthreads();
    }

    int r0 = row0 + wid * 16 + g;
    int r1 = r0 + 8;
    bool ok0 = (r0 < N_NODES), ok1 = (r1 < N_NODES);
#pragma unroll
    for (int nt = 0; nt < 8; nt++) {
        int col = nt * 8 + 2 * t;
        float2 bv = *(const float2*)(b + col);
        if (ok0) {
            float2 v = make_float2(acc[nt][0] + bv.x, acc[nt][1] + bv.y);
            *(float2*)(out + (size_t)r0 * REPR + col) = v;
        }
        if (ok1) {
            float2 v = make_float2(acc[nt][2] + bv.x, acc[nt][3] + bv.y);
            *(float2*)(out + (size_t)r1 * REPR + col) = v;
        }
    }
}

// ---------------------------------------------------------------------------
// Launch. Stream fork: csr_fill runs concurrently with layer-0 GEMM (both
// depend only on the scan). Host-side stream/event setup happens only during
// capture; the parallelism is baked into the replayed graph.
// ---------------------------------------------------------------------------
extern "C" void kernel_launch(void* const* d_in, const int* in_sizes, int n_in,
                              void* d_out, int out_size)
{
    const float* x    = (const float*)d_in[0];
    const void*  ei   = d_in[1];
    const float* W1   = (const float*)d_in[2];
    const float* b1   = (const float*)d_in[3];
    const float* W2   = (const float*)d_in[4];
    const float* b2   = (const float*)d_in[5];
    const float* W3   = (const float*)d_in[6];
    const float* b3   = (const float*)d_in[7];
    const float* Wlin = (const float*)d_in[8];
    const float* blin = (const float*)d_in[9];
    float*       out  = (float*)d_out;

    const int node_blocks = (N_NODES + 255) / 256;
    const int edge_blocks = (N_EDGES + 255) / 256;
    const int gemm_blocks = (N_NODES + 127) / 128;
    const int warp_blocks = (N_NODES * 32 + 255) / 256;

    k_prep      <<<node_blocks, 256>>>((const int*)ei);
    k_count     <<<edge_blocks, 256>>>(ei);
    k_block_sums<<<SCAN_NBLK, SCAN_B>>>();
    k_scan_bsums<<<1, 512>>>();
    k_scan_final<<<SCAN_NBLK, SCAN_B>>>();

    // Fork: csr_fill on s1, layer-0 GEMM on the main stream.
    cudaStream_t s1;
    cudaStreamCreateWithFlags(&s1, cudaStreamNonBlocking);
    cudaEvent_t ev_fork, ev_join;
    cudaEventCreateWithFlags(&ev_fork, cudaEventDisableTiming);
    cudaEventCreateWithFlags(&ev_join, cudaEventDisableTiming);

    cudaEventRecord(ev_fork, 0);
    cudaStreamWaitEvent(s1, ev_fork, 0);
    k_csr_fill<<<edge_blocks, 256, 0, s1>>>(ei);
    cudaEventRecord(ev_join, s1);

    k_gemm_layer<<<gemm_blocks, 256>>>(x, 0, W1);
    cudaStreamWaitEvent(0, ev_join, 0);   // join before gather needs CSR

    const float* Wl[3] = {W1, W2, W3};
    const float* bl[3] = {b1, b2, b3};
    for (int l = 0; l < 3; l++) {
        if (l > 0) k_gemm_layer<<<gemm_blocks, 256>>>(x, l, Wl[l]);
        k_gather<<<warp_blocks, 256>>>(bl[l], l);
    }

    k_gemm_final<<<gemm_blocks, 256>>>(Wlin, blin, out);

    cudaEventDestroy(ev_fork);
    cudaEventDestroy(ev_join);
    cudaStreamDestroy(s1);
}